// round 6
// baseline (speedup 1.0000x reference)
#include <cuda_runtime.h>
#include <cuda_fp16.h>

#define NU   200000
#define NI   100000
#define NN   300000
#define DIM  64
#define MAXE 2000000
#define E2   (2*MAXE)
#define NBRCAP (E2 + 3*NN + 64)   // CSR segments padded to 4-alignment

// ---------------- static device scratch ----------------
__device__ __align__(16) int     g_deg[NN];
__device__ __align__(16) int     g_start[NN];
__device__ __align__(16) int     g_cursor[NN];
__device__                int    g_total;
__device__ __align__(16) float   g_invdeg[NN];
__device__ __align__(16) float   g_en[NN];
__device__ __align__(16) __half2 g_egoh[(size_t)NN * 32];
__device__ __align__(16) int     g_nbr[NBRCAP];
__device__ __align__(16) __half2 g_xs0[(size_t)NN * 32];
__device__ __align__(16) __half2 g_xs1[(size_t)NN * 32];

// ---------------- helpers ----------------
__device__ __forceinline__ unsigned hadd2u(unsigned a, unsigned b) {
    __half2 ha = *reinterpret_cast<__half2*>(&a);
    __half2 hb = *reinterpret_cast<__half2*>(&b);
    __half2 r  = __hadd2(ha, hb);
    return *reinterpret_cast<unsigned*>(&r);
}
__device__ __forceinline__ float2 h2f(unsigned a) {
    return __half22float2(*reinterpret_cast<__half2*>(&a));
}

// ---------------- setup kernels ----------------

__global__ void k_count(const int* __restrict__ rows, const int* __restrict__ cols, int E) {
    int i = blockIdx.x * blockDim.x + threadIdx.x;
    if (i < E) {
        atomicAdd(&g_deg[rows[i]], 1);
        atomicAdd(&g_deg[cols[i] + NU], 1);
    }
}

// Block of 256 nodes: block-scan of 4-padded degrees (one atomic per block
// reserves the range -> every CSR segment starts 16B-aligned), invdeg, |ego|
// fp32-exact, ego->fp16, xs0 = invdeg*ego (fp16).
__global__ void k_assign(const float* __restrict__ ue, const float* __restrict__ ie) {
    __shared__ float sh_iv[256];
    __shared__ int   sh_ws[8];
    __shared__ int   sh_base;

    int tid  = threadIdx.x;
    int lane = tid & 31, wid = tid >> 5;
    int base = blockIdx.x * 256;
    int node = base + tid;

    int d = (node < NN) ? g_deg[node] : 0;
    int p = (d + 3) & ~3;

    int x = p;
    #pragma unroll
    for (int o = 1; o < 32; o <<= 1) {
        int t = __shfl_up_sync(0xffffffffu, x, o);
        if (lane >= o) x += t;
    }
    if (lane == 31) sh_ws[wid] = x;
    __syncthreads();
    if (wid == 0) {
        int s = (lane < 8) ? sh_ws[lane] : 0;
        #pragma unroll
        for (int o = 1; o < 8; o <<= 1) {
            int t = __shfl_up_sync(0xffffffffu, s, o);
            if (lane >= o) s += t;
        }
        if (lane < 8) sh_ws[lane] = s;
    }
    __syncthreads();
    if (tid == 0) sh_base = atomicAdd(&g_total, sh_ws[7]);
    __syncthreads();

    int excl = (wid ? sh_ws[wid - 1] : 0) + x - p;
    float iv = rsqrtf((float)d + 1e-7f);
    if (node < NN) {
        int st = sh_base + excl;
        g_start[node]  = st;
        g_cursor[node] = st;
        g_invdeg[node] = iv;
    }
    sh_iv[tid] = iv;
    __syncthreads();

    #pragma unroll 1
    for (int i = 0; i < 32; i++) {
        int ln = wid * 32 + i;
        int n  = base + ln;
        if (n >= NN) break;
        const float* ego = (n < NU) ? (ue + (size_t)n * DIM) : (ie + (size_t)(n - NU) * DIM);
        float2 e = *reinterpret_cast<const float2*>(ego + lane * 2);
        float en = e.x * e.x + e.y * e.y;
        #pragma unroll
        for (int o = 16; o; o >>= 1) en += __shfl_xor_sync(0xffffffffu, en, o);
        if (lane == 0) g_en[n] = fmaxf(sqrtf(en), 1e-8f);
        float ivn = sh_iv[ln];
        size_t q = (size_t)n * 32 + lane;
        g_egoh[q] = __floats2half2_rn(e.x, e.y);
        g_xs0[q]  = __floats2half2_rn(ivn * e.x, ivn * e.y);
    }
}

__global__ void k_fill(const int* __restrict__ rows, const int* __restrict__ cols, int E) {
    int i = blockIdx.x * blockDim.x + threadIdx.x;
    if (i < E) {
        int u = rows[i];
        int v = cols[i] + NU;
        int p = atomicAdd(&g_cursor[u], 1);
        g_nbr[p] = v;
        int q = atomicAdd(&g_cursor[v], 1);
        g_nbr[q] = u;
    }
}

// ---------------- fused layer: 1 node per warp, 32 lanes x half2 ----------------
// Warp-uniform loop bounds (no divergence); each gather LDG.32 covers exactly
// one 128B line; neighbor indices are warp-uniform int4 broadcasts.
template <bool FIRST, bool LAST, bool FLIP>
__global__ void k_layer(float* __restrict__ acc) {
    const unsigned* __restrict__ xin  = reinterpret_cast<const unsigned*>(FLIP ? g_xs1 : g_xs0);
    unsigned*       __restrict__ xout = reinterpret_cast<unsigned*>(FLIP ? g_xs0 : g_xs1);

    int node = blockIdx.x * (blockDim.x >> 5) + (threadIdx.x >> 5);  // exact grid
    int lane = threadIdx.x & 31;

    int start = g_start[node];
    int end   = start + g_deg[node];

    // hoisted epilogue operands
    float iv = g_invdeg[node];
    float en = g_en[node];
    unsigned ev = reinterpret_cast<const unsigned*>(g_egoh)[(size_t)node * 32 + lane];

    float h0 = 0.f, h1 = 0.f;
    int j = start;
    for (; j + 4 <= end; j += 4) {
        int4 ii = *reinterpret_cast<const int4*>(g_nbr + j);   // warp-uniform
        unsigned v0 = xin[(size_t)ii.x * 32 + lane];
        unsigned v1 = xin[(size_t)ii.y * 32 + lane];
        unsigned v2 = xin[(size_t)ii.z * 32 + lane];
        unsigned v3 = xin[(size_t)ii.w * 32 + lane];
        unsigned a01 = hadd2u(v0, v1);                          // pairwise fp16
        unsigned a23 = hadd2u(v2, v3);
        float2 f;
        f = h2f(a01); h0 += f.x; h1 += f.y;
        f = h2f(a23); h0 += f.x; h1 += f.y;
    }
    for (; j < end; ++j) {
        unsigned v = xin[(size_t)g_nbr[j] * 32 + lane];
        float2 f = h2f(v); h0 += f.x; h1 += f.y;
    }

    h0 *= iv; h1 *= iv;

    float2 e = h2f(ev);
    float dot = h0 * e.x + h1 * e.y;
    float hn  = h0 * h0 + h1 * h1;
    #pragma unroll
    for (int o = 16; o; o >>= 1) {
        dot += __shfl_xor_sync(0xffffffffu, dot, o);
        hn  += __shfl_xor_sync(0xffffffffu, hn,  o);
    }

    float wgt = dot / (fmaxf(sqrtf(hn), 1e-8f) * en);
    float o0 = wgt * h0, o1 = wgt * h1;

    float2* ap = reinterpret_cast<float2*>(acc + (size_t)node * DIM + lane * 2);
    if (FIRST) {
        float2 o; o.x = o0; o.y = o1;
        *ap = o;
    } else {
        float2 a2 = *ap;
        a2.x += o0; a2.y += o1;
        *ap = a2;
    }
    if (!LAST) {
        __half2 pk = __floats2half2_rn(iv * o0, iv * o1);
        xout[(size_t)node * 32 + lane] = *reinterpret_cast<unsigned*>(&pk);
    }
}

// ---------------- launch ----------------

extern "C" void kernel_launch(void* const* d_in, const int* in_sizes, int n_in,
                              void* d_out, int out_size) {
    const float* ue   = (const float*)d_in[0];
    const float* ie   = (const float*)d_in[1];
    const int*   rows = (const int*)d_in[2];
    const int*   cols = (const int*)d_in[3];
    int E = in_sizes[2];
    if (E > MAXE) E = MAXE;
    float* acc = (float*)d_out;

    void* p_deg = nullptr;
    void* p_tot = nullptr;
    cudaGetSymbolAddress(&p_deg, g_deg);
    cudaGetSymbolAddress(&p_tot, g_total);
    cudaMemsetAsync(p_deg, 0, sizeof(int) * NN);
    cudaMemsetAsync(p_tot, 0, sizeof(int));

    const int T = 256;
    k_count <<<(E + T - 1) / T, T>>>(rows, cols, E);        // launch 0
    k_assign<<<(NN + 255) / 256, 256>>>(ue, ie);            // launch 1
    k_fill  <<<(E + T - 1) / T, T>>>(rows, cols, E);        // launch 2

    const int LBLK = NN / 8;   // 1 node/warp, 8 warps/block = 37500 blocks (exact)
    k_layer<true,  false, false><<<LBLK, T>>>(acc);         // launch 3 (ncu target)
    k_layer<false, false, true ><<<LBLK, T>>>(acc);         // launch 4
    k_layer<false, true,  false><<<LBLK, T>>>(acc);         // launch 5
}

// round 7
// speedup vs baseline: 1.4417x; 1.4417x over previous
#include <cuda_runtime.h>
#include <cuda_fp16.h>

#define NU   200000
#define NI   100000
#define NN   300000
#define DIM  64
#define MAXE 2000000
#define E2   (2*MAXE)
#define NBRCAP (E2 + 3*NN + 64)   // CSR segments padded to multiples of 4

// ---------------- static device scratch ----------------
__device__ __align__(16) int     g_deg[NN];
__device__ __align__(16) int     g_start[NN];
__device__ __align__(16) int     g_cursor[NN];
__device__                int    g_total;
__device__ __align__(16) float   g_invdeg[NN];
__device__ __align__(16) float   g_en[NN];
__device__ __align__(16) __half2 g_egoh[(size_t)NN * 32];
__device__ __align__(16) int     g_nbr[NBRCAP];
// one extra row (index NN) kept all-zero: target of CSR pad slots
__device__ __align__(16) __half2 g_xs0[(size_t)(NN + 1) * 32];
__device__ __align__(16) __half2 g_xs1[(size_t)(NN + 1) * 32];

// ---------------- helpers ----------------
__device__ __forceinline__ unsigned hadd2u(unsigned a, unsigned b) {
    __half2 ha = *reinterpret_cast<__half2*>(&a);
    __half2 hb = *reinterpret_cast<__half2*>(&b);
    __half2 r  = __hadd2(ha, hb);
    return *reinterpret_cast<unsigned*>(&r);
}
__device__ __forceinline__ float2 h2f(unsigned a) {
    return __half22float2(*reinterpret_cast<__half2*>(&a));
}

// ---------------- setup kernels ----------------

__global__ void k_count(const int* __restrict__ rows, const int* __restrict__ cols, int E) {
    int i = blockIdx.x * blockDim.x + threadIdx.x;
    if (i < E) {
        atomicAdd(&g_deg[rows[i]], 1);
        atomicAdd(&g_deg[cols[i] + NU], 1);
    }
}

// Block of 256 nodes: block-scan of 4-padded degrees (one atomic per block),
// write dummy index NN into pad slots, invdeg, |ego| fp32-exact, ego->fp16,
// xs0 = invdeg*ego (fp16). Also zeroes the dummy row NN of xs0/xs1.
__global__ void k_assign(const float* __restrict__ ue, const float* __restrict__ ie) {
    __shared__ float sh_iv[256];
    __shared__ int   sh_ws[8];
    __shared__ int   sh_base;

    int tid  = threadIdx.x;
    int lane = tid & 31, wid = tid >> 5;
    int base = blockIdx.x * 256;
    int node = base + tid;

    int d = (node < NN) ? g_deg[node] : 0;
    int p = (d + 3) & ~3;

    int x = p;
    #pragma unroll
    for (int o = 1; o < 32; o <<= 1) {
        int t = __shfl_up_sync(0xffffffffu, x, o);
        if (lane >= o) x += t;
    }
    if (lane == 31) sh_ws[wid] = x;
    __syncthreads();
    if (wid == 0) {
        int s = (lane < 8) ? sh_ws[lane] : 0;
        #pragma unroll
        for (int o = 1; o < 8; o <<= 1) {
            int t = __shfl_up_sync(0xffffffffu, s, o);
            if (lane >= o) s += t;
        }
        if (lane < 8) sh_ws[lane] = s;
    }
    __syncthreads();
    if (tid == 0) sh_base = atomicAdd(&g_total, sh_ws[7]);
    __syncthreads();

    int excl = (wid ? sh_ws[wid - 1] : 0) + x - p;
    float iv = rsqrtf((float)d + 1e-7f);
    if (node < NN) {
        int st = sh_base + excl;
        g_start[node]  = st;
        g_cursor[node] = st;
        g_invdeg[node] = iv;
        for (int k = d; k < p; ++k) g_nbr[st + k] = NN;   // pad -> zero row
    }
    sh_iv[tid] = iv;

    if (blockIdx.x == 0 && tid < 32) {                    // zero dummy row
        __half2 z = __floats2half2_rn(0.f, 0.f);
        g_xs0[(size_t)NN * 32 + tid] = z;
        g_xs1[(size_t)NN * 32 + tid] = z;
    }
    __syncthreads();

    #pragma unroll 1
    for (int i = 0; i < 32; i++) {
        int ln = wid * 32 + i;
        int n  = base + ln;
        if (n >= NN) break;
        const float* ego = (n < NU) ? (ue + (size_t)n * DIM) : (ie + (size_t)(n - NU) * DIM);
        float2 e = *reinterpret_cast<const float2*>(ego + lane * 2);
        float en = e.x * e.x + e.y * e.y;
        #pragma unroll
        for (int o = 16; o; o >>= 1) en += __shfl_xor_sync(0xffffffffu, en, o);
        if (lane == 0) g_en[n] = fmaxf(sqrtf(en), 1e-8f);
        float ivn = sh_iv[ln];
        size_t q = (size_t)n * 32 + lane;
        g_egoh[q] = __floats2half2_rn(e.x, e.y);
        g_xs0[q]  = __floats2half2_rn(ivn * e.x, ivn * e.y);
    }
}

__global__ void k_fill(const int* __restrict__ rows, const int* __restrict__ cols, int E) {
    int i = blockIdx.x * blockDim.x + threadIdx.x;
    if (i < E) {
        int u = rows[i];
        int v = cols[i] + NU;
        int p = atomicAdd(&g_cursor[u], 1);
        g_nbr[p] = v;
        int q = atomicAdd(&g_cursor[v], 1);
        g_nbr[q] = u;
    }
}

// ------- fused layer: 4 nodes/warp, 8 lanes/node, uint4 (16B) per lane -------
// One LDG.128 per edge per 8-lane group (4 rows per warp instruction); padded
// CSR (dummy zero row) kills all remainder code; level-2 HADD2 tree.
template <bool FIRST, bool LAST, bool FLIP>
__global__ void __launch_bounds__(256, 6) k_layer(float* __restrict__ acc) {
    const uint4* __restrict__ xin  = reinterpret_cast<const uint4*>(FLIP ? g_xs1 : g_xs0);
    uint4*       __restrict__ xout = reinterpret_cast<uint4*>(FLIP ? g_xs0 : g_xs1);

    int warp  = blockIdx.x * (blockDim.x >> 5) + (threadIdx.x >> 5);
    int grp   = (threadIdx.x >> 3) & 3;
    int node  = warp * 4 + grp;              // exact grid: node < NN always
    int lane8 = threadIdx.x & 7;

    int start = g_start[node];
    int trips = (g_deg[node] + 3) >> 2;      // padded slots point at zero row

    // hoisted epilogue operands
    float iv = g_invdeg[node];
    float en = g_en[node];
    uint4 ev = reinterpret_cast<const uint4*>(g_egoh)[(size_t)node * 8 + lane8];

    // warp-uniform trip bound (groups differ -> guard below)
    int tmax = trips;
    tmax = max(tmax, __shfl_xor_sync(0xffffffffu, tmax, 8));
    tmax = max(tmax, __shfl_xor_sync(0xffffffffu, tmax, 16));

    float h0 = 0.f, h1 = 0.f, h2 = 0.f, h3 = 0.f;
    float h4 = 0.f, h5 = 0.f, h6 = 0.f, h7 = 0.f;

    const int4* ip = reinterpret_cast<const int4*>(g_nbr + start);
    for (int t = 0; t < tmax; ++t) {
        if (t < trips) {
            int4 ii = ip[t];
            uint4 v0 = xin[(size_t)ii.x * 8 + lane8];
            uint4 v1 = xin[(size_t)ii.y * 8 + lane8];
            uint4 v2 = xin[(size_t)ii.z * 8 + lane8];
            uint4 v3 = xin[(size_t)ii.w * 8 + lane8];
            unsigned ax = hadd2u(v0.x, v1.x), bx = hadd2u(v2.x, v3.x);
            unsigned ay = hadd2u(v0.y, v1.y), by = hadd2u(v2.y, v3.y);
            unsigned az = hadd2u(v0.z, v1.z), bz = hadd2u(v2.z, v3.z);
            unsigned aw = hadd2u(v0.w, v1.w), bw = hadd2u(v2.w, v3.w);
            unsigned sx = hadd2u(ax, bx);
            unsigned sy = hadd2u(ay, by);
            unsigned sz = hadd2u(az, bz);
            unsigned sw = hadd2u(aw, bw);
            float2 f;
            f = h2f(sx); h0 += f.x; h1 += f.y;
            f = h2f(sy); h2 += f.x; h3 += f.y;
            f = h2f(sz); h4 += f.x; h5 += f.y;
            f = h2f(sw); h6 += f.x; h7 += f.y;
        }
    }

    h0 *= iv; h1 *= iv; h2 *= iv; h3 *= iv;
    h4 *= iv; h5 *= iv; h6 *= iv; h7 *= iv;

    float2 e0 = h2f(ev.x), e1 = h2f(ev.y), e2 = h2f(ev.z), e3 = h2f(ev.w);

    float dot = h0 * e0.x + h1 * e0.y + h2 * e1.x + h3 * e1.y
              + h4 * e2.x + h5 * e2.y + h6 * e3.x + h7 * e3.y;
    float hn  = h0 * h0 + h1 * h1 + h2 * h2 + h3 * h3
              + h4 * h4 + h5 * h5 + h6 * h6 + h7 * h7;
    #pragma unroll
    for (int o = 4; o; o >>= 1) {            // reduce within 8-lane group
        dot += __shfl_xor_sync(0xffffffffu, dot, o);
        hn  += __shfl_xor_sync(0xffffffffu, hn,  o);
    }

    float wgt = dot / (fmaxf(sqrtf(hn), 1e-8f) * en);
    float o0 = wgt * h0, o1 = wgt * h1, o2 = wgt * h2, o3 = wgt * h3;
    float o4 = wgt * h4, o5 = wgt * h5, o6 = wgt * h6, o7 = wgt * h7;

    float4* ap = reinterpret_cast<float4*>(acc + (size_t)node * DIM + lane8 * 8);
    if (FIRST) {
        float4 A; A.x = o0; A.y = o1; A.z = o2; A.w = o3;
        float4 B; B.x = o4; B.y = o5; B.z = o6; B.w = o7;
        ap[0] = A; ap[1] = B;
    } else {
        float4 A = ap[0], B = ap[1];
        A.x += o0; A.y += o1; A.z += o2; A.w += o3;
        B.x += o4; B.y += o5; B.z += o6; B.w += o7;
        ap[0] = A; ap[1] = B;
    }
    if (!LAST) {
        __half2 p0 = __floats2half2_rn(iv * o0, iv * o1);
        __half2 p1 = __floats2half2_rn(iv * o2, iv * o3);
        __half2 p2 = __floats2half2_rn(iv * o4, iv * o5);
        __half2 p3 = __floats2half2_rn(iv * o6, iv * o7);
        uint4 xo;
        xo.x = *reinterpret_cast<unsigned*>(&p0);
        xo.y = *reinterpret_cast<unsigned*>(&p1);
        xo.z = *reinterpret_cast<unsigned*>(&p2);
        xo.w = *reinterpret_cast<unsigned*>(&p3);
        xout[(size_t)node * 8 + lane8] = xo;
    }
}

// ---------------- launch ----------------

extern "C" void kernel_launch(void* const* d_in, const int* in_sizes, int n_in,
                              void* d_out, int out_size) {
    const float* ue   = (const float*)d_in[0];
    const float* ie   = (const float*)d_in[1];
    const int*   rows = (const int*)d_in[2];
    const int*   cols = (const int*)d_in[3];
    int E = in_sizes[2];
    if (E > MAXE) E = MAXE;
    float* acc = (float*)d_out;

    void* p_deg = nullptr;
    void* p_tot = nullptr;
    cudaGetSymbolAddress(&p_deg, g_deg);
    cudaGetSymbolAddress(&p_tot, g_total);
    cudaMemsetAsync(p_deg, 0, sizeof(int) * NN);
    cudaMemsetAsync(p_tot, 0, sizeof(int));

    const int T = 256;
    k_count <<<(E + T - 1) / T, T>>>(rows, cols, E);        // launch 0
    k_assign<<<(NN + 255) / 256, 256>>>(ue, ie);            // launch 1
    k_fill  <<<(E + T - 1) / T, T>>>(rows, cols, E);        // launch 2

    const int LBLK = NN / 4 / 8;   // 4 nodes/warp, 8 warps/block = 9375 blocks (exact)
    k_layer<true,  false, false><<<LBLK, T>>>(acc);         // launch 3 (ncu target)
    k_layer<false, false, true ><<<LBLK, T>>>(acc);         // launch 4
    k_layer<false, true,  false><<<LBLK, T>>>(acc);         // launch 5
}

// round 8
// speedup vs baseline: 1.4474x; 1.0039x over previous
#include <cuda_runtime.h>
#include <cuda_fp16.h>

#define NU   200000
#define NI   100000
#define NN   300000
#define DIM  64
#define MAXE 2000000
#define E2   (2*MAXE)
#define NBRCAP (E2 + 3*NN + 64)   // CSR segments padded to multiples of 4
#define NBKT 16

// ---------------- static device scratch ----------------
// single zero-initialized block: deg | total | bucket hist | bucket cursors
__device__ __align__(16) int g_zeroblk[NN + 1 + NBKT + NBKT];
#define g_deg   (g_zeroblk)
#define g_total (g_zeroblk + NN)
#define g_bhist (g_zeroblk + NN + 1)
#define g_bcur  (g_zeroblk + NN + 1 + NBKT)

__device__ __align__(16) int     g_start[NN];
__device__ __align__(16) int     g_cursor[NN];
__device__ __align__(16) int     g_order[NN];
__device__ __align__(16) float   g_invdeg[NN];
__device__ __align__(16) float   g_en[NN];
__device__ __align__(16) __half2 g_egoh[(size_t)NN * 32];
__device__ __align__(16) int     g_nbr[NBRCAP];
// one extra row (index NN) kept all-zero: target of CSR pad slots
__device__ __align__(16) __half2 g_xs0[(size_t)(NN + 1) * 32];
__device__ __align__(16) __half2 g_xs1[(size_t)(NN + 1) * 32];

// ---------------- helpers ----------------
__device__ __forceinline__ unsigned hadd2u(unsigned a, unsigned b) {
    __half2 ha = *reinterpret_cast<__half2*>(&a);
    __half2 hb = *reinterpret_cast<__half2*>(&b);
    __half2 r  = __hadd2(ha, hb);
    return *reinterpret_cast<unsigned*>(&r);
}
__device__ __forceinline__ float2 h2f(unsigned a) {
    return __half22float2(*reinterpret_cast<__half2*>(&a));
}
__device__ __forceinline__ int bucket_of(int d) {
    int t = (d + 3) >> 2;
    return t < NBKT ? t : NBKT - 1;
}

// ---------------- setup kernels ----------------

// 2 edges per thread (E is even for this dataset; tail loop guards anyway)
__global__ void k_count(const int* __restrict__ rows, const int* __restrict__ cols, int E) {
    int i = (blockIdx.x * blockDim.x + threadIdx.x) * 2;
    if (i + 1 < E) {
        int2 r = *reinterpret_cast<const int2*>(rows + i);
        int2 c = *reinterpret_cast<const int2*>(cols + i);
        atomicAdd(&g_deg[r.x], 1);
        atomicAdd(&g_deg[r.y], 1);
        atomicAdd(&g_deg[c.x + NU], 1);
        atomicAdd(&g_deg[c.y + NU], 1);
    } else if (i < E) {
        atomicAdd(&g_deg[rows[i]], 1);
        atomicAdd(&g_deg[cols[i] + NU], 1);
    }
}

// Block of 256 nodes: block-scan of 4-padded degrees (one atomic per block),
// pad slots -> dummy zero row, invdeg, |ego| fp32-exact, ego->fp16,
// xs0 = invdeg*ego. Also: bucket histogram (smem-privatized) for node sort.
__global__ void k_assign(const float* __restrict__ ue, const float* __restrict__ ie) {
    __shared__ float sh_iv[256];
    __shared__ int   sh_ws[8];
    __shared__ int   sh_base;
    __shared__ int   sh_h[NBKT];

    int tid  = threadIdx.x;
    int lane = tid & 31, wid = tid >> 5;
    int base = blockIdx.x * 256;
    int node = base + tid;

    if (tid < NBKT) sh_h[tid] = 0;

    int d = (node < NN) ? g_deg[node] : 0;
    int p = (d + 3) & ~3;

    int x = p;
    #pragma unroll
    for (int o = 1; o < 32; o <<= 1) {
        int t = __shfl_up_sync(0xffffffffu, x, o);
        if (lane >= o) x += t;
    }
    if (lane == 31) sh_ws[wid] = x;
    __syncthreads();
    if (wid == 0) {
        int s = (lane < 8) ? sh_ws[lane] : 0;
        #pragma unroll
        for (int o = 1; o < 8; o <<= 1) {
            int t = __shfl_up_sync(0xffffffffu, s, o);
            if (lane >= o) s += t;
        }
        if (lane < 8) sh_ws[lane] = s;
    }
    __syncthreads();
    if (tid == 0) sh_base = atomicAdd(g_total, sh_ws[7]);
    if (node < NN) atomicAdd(&sh_h[bucket_of(d)], 1);
    __syncthreads();

    if (tid < NBKT && sh_h[tid]) atomicAdd(&g_bhist[tid], sh_h[tid]);

    int excl = (wid ? sh_ws[wid - 1] : 0) + x - p;
    float iv = rsqrtf((float)d + 1e-7f);
    if (node < NN) {
        int st = sh_base + excl;
        g_start[node]  = st;
        g_cursor[node] = st;
        g_invdeg[node] = iv;
        for (int k = d; k < p; ++k) g_nbr[st + k] = NN;   // pad -> zero row
    }
    sh_iv[tid] = iv;

    if (blockIdx.x == 0 && tid < 32) {                    // zero dummy row
        __half2 z = __floats2half2_rn(0.f, 0.f);
        g_xs0[(size_t)NN * 32 + tid] = z;
        g_xs1[(size_t)NN * 32 + tid] = z;
    }
    __syncthreads();

    #pragma unroll 1
    for (int i = 0; i < 32; i++) {
        int ln = wid * 32 + i;
        int n  = base + ln;
        if (n >= NN) break;
        const float* ego = (n < NU) ? (ue + (size_t)n * DIM) : (ie + (size_t)(n - NU) * DIM);
        float2 e = *reinterpret_cast<const float2*>(ego + lane * 2);
        float en = e.x * e.x + e.y * e.y;
        #pragma unroll
        for (int o = 16; o; o >>= 1) en += __shfl_xor_sync(0xffffffffu, en, o);
        if (lane == 0) g_en[n] = fmaxf(sqrtf(en), 1e-8f);
        float ivn = sh_iv[ln];
        size_t q = (size_t)n * 32 + lane;
        g_egoh[q] = __floats2half2_rn(e.x, e.y);
        g_xs0[q]  = __floats2half2_rn(ivn * e.x, ivn * e.y);
    }
}

// Counting-sort scatter: node -> g_order, grouped by trip-count bucket.
__global__ void k_order() {
    __shared__ int sh_cnt[NBKT];
    __shared__ int sh_base[NBKT];

    int tid  = threadIdx.x;
    int node = blockIdx.x * 256 + tid;

    if (tid < NBKT) sh_cnt[tid] = 0;
    __syncthreads();

    int b = 0, r = 0;
    bool ok = (node < NN);
    if (ok) {
        b = bucket_of(g_deg[node]);
        r = atomicAdd(&sh_cnt[b], 1);
    }
    __syncthreads();

    if (tid < NBKT) {
        int c = sh_cnt[tid];
        int bb = c ? atomicAdd(&g_bcur[tid], c) : 0;
        int gb = 0;
        #pragma unroll
        for (int j = 0; j < NBKT; j++) gb += (j < tid) ? g_bhist[j] : 0;
        sh_base[tid] = gb + bb;
    }
    __syncthreads();

    if (ok) g_order[sh_base[b] + r] = node;
}

__global__ void k_fill(const int* __restrict__ rows, const int* __restrict__ cols, int E) {
    int i = (blockIdx.x * blockDim.x + threadIdx.x) * 2;
    if (i + 1 < E) {
        int2 rr = *reinterpret_cast<const int2*>(rows + i);
        int2 cc = *reinterpret_cast<const int2*>(cols + i);
        int v0 = cc.x + NU, v1 = cc.y + NU;
        int p0 = atomicAdd(&g_cursor[rr.x], 1);
        int p1 = atomicAdd(&g_cursor[rr.y], 1);
        int q0 = atomicAdd(&g_cursor[v0], 1);
        int q1 = atomicAdd(&g_cursor[v1], 1);
        g_nbr[p0] = v0; g_nbr[p1] = v1;
        g_nbr[q0] = rr.x; g_nbr[q1] = rr.y;
    } else if (i < E) {
        int u = rows[i];
        int v = cols[i] + NU;
        int p = atomicAdd(&g_cursor[u], 1);
        g_nbr[p] = v;
        int q = atomicAdd(&g_cursor[v], 1);
        g_nbr[q] = u;
    }
}

// ------- fused layer: 4 nodes/warp (bucket-sorted), 8 lanes/node, uint4/lane -------
template <bool FIRST, bool LAST, bool FLIP>
__global__ void __launch_bounds__(128, 12) k_layer(float* __restrict__ acc) {
    const uint4* __restrict__ xin  = reinterpret_cast<const uint4*>(FLIP ? g_xs1 : g_xs0);
    uint4*       __restrict__ xout = reinterpret_cast<uint4*>(FLIP ? g_xs0 : g_xs1);

    int warp  = blockIdx.x * (blockDim.x >> 5) + (threadIdx.x >> 5);
    int grp   = (threadIdx.x >> 3) & 3;
    int node  = g_order[warp * 4 + grp];     // bucket-sorted: near-uniform trips
    int lane8 = threadIdx.x & 7;

    int start = g_start[node];
    int trips = (g_deg[node] + 3) >> 2;

    float iv = g_invdeg[node];
    float en = g_en[node];
    uint4 ev = reinterpret_cast<const uint4*>(g_egoh)[(size_t)node * 8 + lane8];

    int tmax = trips;
    tmax = max(tmax, __shfl_xor_sync(0xffffffffu, tmax, 8));
    tmax = max(tmax, __shfl_xor_sync(0xffffffffu, tmax, 16));

    float h0 = 0.f, h1 = 0.f, h2 = 0.f, h3 = 0.f;
    float h4 = 0.f, h5 = 0.f, h6 = 0.f, h7 = 0.f;

    const int4* ip = reinterpret_cast<const int4*>(g_nbr + start);
    for (int t = 0; t < tmax; ++t) {
        if (t < trips) {
            int4 ii = ip[t];
            uint4 v0 = xin[(size_t)ii.x * 8 + lane8];
            uint4 v1 = xin[(size_t)ii.y * 8 + lane8];
            uint4 v2 = xin[(size_t)ii.z * 8 + lane8];
            uint4 v3 = xin[(size_t)ii.w * 8 + lane8];
            unsigned ax = hadd2u(v0.x, v1.x), bx = hadd2u(v2.x, v3.x);
            unsigned ay = hadd2u(v0.y, v1.y), by = hadd2u(v2.y, v3.y);
            unsigned az = hadd2u(v0.z, v1.z), bz = hadd2u(v2.z, v3.z);
            unsigned aw = hadd2u(v0.w, v1.w), bw = hadd2u(v2.w, v3.w);
            unsigned sx = hadd2u(ax, bx);
            unsigned sy = hadd2u(ay, by);
            unsigned sz = hadd2u(az, bz);
            unsigned sw = hadd2u(aw, bw);
            float2 f;
            f = h2f(sx); h0 += f.x; h1 += f.y;
            f = h2f(sy); h2 += f.x; h3 += f.y;
            f = h2f(sz); h4 += f.x; h5 += f.y;
            f = h2f(sw); h6 += f.x; h7 += f.y;
        }
    }

    h0 *= iv; h1 *= iv; h2 *= iv; h3 *= iv;
    h4 *= iv; h5 *= iv; h6 *= iv; h7 *= iv;

    float2 e0 = h2f(ev.x), e1 = h2f(ev.y), e2 = h2f(ev.z), e3 = h2f(ev.w);

    float dot = h0 * e0.x + h1 * e0.y + h2 * e1.x + h3 * e1.y
              + h4 * e2.x + h5 * e2.y + h6 * e3.x + h7 * e3.y;
    float hn  = h0 * h0 + h1 * h1 + h2 * h2 + h3 * h3
              + h4 * h4 + h5 * h5 + h6 * h6 + h7 * h7;
    #pragma unroll
    for (int o = 4; o; o >>= 1) {
        dot += __shfl_xor_sync(0xffffffffu, dot, o);
        hn  += __shfl_xor_sync(0xffffffffu, hn,  o);
    }

    float wgt = dot / (fmaxf(sqrtf(hn), 1e-8f) * en);
    float o0 = wgt * h0, o1 = wgt * h1, o2 = wgt * h2, o3 = wgt * h3;
    float o4 = wgt * h4, o5 = wgt * h5, o6 = wgt * h6, o7 = wgt * h7;

    float4* ap = reinterpret_cast<float4*>(acc + (size_t)node * DIM + lane8 * 8);
    if (FIRST) {
        float4 A; A.x = o0; A.y = o1; A.z = o2; A.w = o3;
        float4 B; B.x = o4; B.y = o5; B.z = o6; B.w = o7;
        ap[0] = A; ap[1] = B;
    } else {
        float4 A = ap[0], B = ap[1];
        A.x += o0; A.y += o1; A.z += o2; A.w += o3;
        B.x += o4; B.y += o5; B.z += o6; B.w += o7;
        ap[0] = A; ap[1] = B;
    }
    if (!LAST) {
        __half2 p0 = __floats2half2_rn(iv * o0, iv * o1);
        __half2 p1 = __floats2half2_rn(iv * o2, iv * o3);
        __half2 p2 = __floats2half2_rn(iv * o4, iv * o5);
        __half2 p3 = __floats2half2_rn(iv * o6, iv * o7);
        uint4 xo;
        xo.x = *reinterpret_cast<unsigned*>(&p0);
        xo.y = *reinterpret_cast<unsigned*>(&p1);
        xo.z = *reinterpret_cast<unsigned*>(&p2);
        xo.w = *reinterpret_cast<unsigned*>(&p3);
        xout[(size_t)node * 8 + lane8] = xo;
    }
}

// ---------------- launch ----------------

extern "C" void kernel_launch(void* const* d_in, const int* in_sizes, int n_in,
                              void* d_out, int out_size) {
    const float* ue   = (const float*)d_in[0];
    const float* ie   = (const float*)d_in[1];
    const int*   rows = (const int*)d_in[2];
    const int*   cols = (const int*)d_in[3];
    int E = in_sizes[2];
    if (E > MAXE) E = MAXE;
    float* acc = (float*)d_out;

    void* p_zero = nullptr;
    cudaGetSymbolAddress(&p_zero, g_zeroblk);
    cudaMemsetAsync(p_zero, 0, sizeof(int) * (NN + 1 + 2 * NBKT));   // launch 0

    const int T = 256;
    int epairs = (E + 1) / 2;
    k_count <<<(epairs + T - 1) / T, T>>>(rows, cols, E);   // launch 1
    k_assign<<<(NN + 255) / 256, 256>>>(ue, ie);            // launch 2
    k_order <<<(NN + 255) / 256, 256>>>();                  // launch 3
    k_fill  <<<(epairs + T - 1) / T, T>>>(rows, cols, E);   // launch 4

    const int LT = 128;                 // 4 warps/block
    const int LBLK = NN / 4 / 4;        // 18750 blocks (exact)
    k_layer<true,  false, false><<<LBLK, LT>>>(acc);        // launch 5 (ncu target)
    k_layer<false, false, true ><<<LBLK, LT>>>(acc);        // launch 6
    k_layer<false, true,  false><<<LBLK, LT>>>(acc);        // launch 7
}